// round 1
// baseline (speedup 1.0000x reference)
#include <cuda_runtime.h>
#include <math.h>

#define CC 2.3026f
#define BATCH 65536

// ---------------- static device scratch (allocation-free rule) ----------------
__device__ float g_m [(long long)BATCH * 512];  // gemm output buffer (reused)
__device__ float g_hA[(long long)BATCH * 512];  // hidden ping
__device__ float g_hB[(long long)BATCH * 256];  // hidden pong
__device__ float g_lam[BATCH];                  // conformal factor per row
// per-column precomputed tables: layer1 @0 (512), layer2 @512 (256), layer3 @768 (128), layer4 @896 (1)
__device__ float g_zn[897];
__device__ float g_chv[897];
__device__ float g_shv[897];

// ---------------- precompute zn = ||z_col||, cosh/sinh(2*cs*r) ----------------
__global__ void prep_kernel(const float* __restrict__ z, const float* __restrict__ r,
                            int fi, int fo, int off)
{
    int k = blockIdx.x * blockDim.x + threadIdx.x;
    if (k >= fo) return;
    float s = 0.f;
    for (int i = 0; i < fi; i++) {
        float v = z[(long long)i * fo + k];
        s = fmaf(v, v, s);
    }
    float zn = fmaxf(sqrtf(s), 1e-15f);
    const float cs = sqrtf(CC);
    float t = 2.f * cs * r[k];
    g_zn[off + k]  = zn;
    g_chv[off + k] = coshf(t);
    g_shv[off + k] = sinhf(t);
}

// ---------------- lam0 = 2 / (1 - c*||x||^2), warp per row (fi=768) ----------------
__global__ void lam0_kernel(const float* __restrict__ x)
{
    int gid  = blockIdx.x * blockDim.x + threadIdx.x;
    int row  = gid >> 5;
    int lane = gid & 31;
    const float4* xr = (const float4*)(x + (long long)row * 768);
    float s = 0.f;
#pragma unroll
    for (int p = 0; p < 6; p++) {
        float4 v = xr[lane + 32 * p];
        s += v.x * v.x + v.y * v.y + v.z * v.z + v.w * v.w;
    }
#pragma unroll
    for (int o = 16; o; o >>= 1) s += __shfl_xor_sync(0xffffffffu, s, o);
    if (lane == 0) g_lam[row] = 2.f / (1.f - CC * s);
}

// ---------------- SGEMM: C[M,N] = A[M,K] @ W[K,N], fp32 ----------------
// BM=128 BN=64 BK=16, 256 threads, thread tile 8x4
__global__ __launch_bounds__(256) void sgemm_kernel(
    const float* __restrict__ A, const float* __restrict__ W, float* __restrict__ Cm,
    int M, int N, int K)
{
    __shared__ float As[16][128];
    __shared__ float Ws[16][64];

    int tid = threadIdx.x;
    int bm = blockIdx.y * 128;
    int bn = blockIdx.x * 64;
    int tx = tid & 15;
    int ty = tid >> 4;

    float acc[8][4];
#pragma unroll
    for (int i = 0; i < 8; i++)
#pragma unroll
        for (int j = 0; j < 4; j++) acc[i][j] = 0.f;

    for (int k0 = 0; k0 < K; k0 += 16) {
        // load A tile: 128 rows x 16 cols = 512 float4, 2 per thread, transpose into As[k][m]
#pragma unroll
        for (int l = 0; l < 2; l++) {
            int idx = tid + 256 * l;
            int row = idx >> 2;
            int kq  = idx & 3;
            float4 a = *(const float4*)(A + (long long)(bm + row) * K + k0 + kq * 4);
            As[kq * 4 + 0][row] = a.x;
            As[kq * 4 + 1][row] = a.y;
            As[kq * 4 + 2][row] = a.z;
            As[kq * 4 + 3][row] = a.w;
        }
        // load W tile: 16 rows x 64 cols = 256 float4, 1 per thread
        {
            int row = tid >> 4;
            int cq  = tid & 15;
            float4 w = *(const float4*)(W + (long long)(k0 + row) * N + bn + cq * 4);
            *(float4*)&Ws[row][cq * 4] = w;
        }
        __syncthreads();

#pragma unroll
        for (int k = 0; k < 16; k++) {
            float a[8], b[4];
#pragma unroll
            for (int i = 0; i < 8; i++) a[i] = As[k][ty * 8 + i];
#pragma unroll
            for (int j = 0; j < 4; j++) b[j] = Ws[k][tx * 4 + j];
#pragma unroll
            for (int i = 0; i < 8; i++)
#pragma unroll
                for (int j = 0; j < 4; j++) acc[i][j] = fmaf(a[i], b[j], acc[i][j]);
        }
        __syncthreads();
    }

#pragma unroll
    for (int i = 0; i < 8; i++) {
        float4 v = make_float4(acc[i][0], acc[i][1], acc[i][2], acc[i][3]);
        *(float4*)(Cm + (long long)(bm + ty * 8 + i) * N + bn + tx * 4) = v;
    }
}

// ---------------- fused hlinear-epilogue + hrelu, warp per row ----------------
// P = fo/32 elements per lane. Also writes lam for the next layer.
template <int P>
__global__ void epi_kernel(const float* __restrict__ m, float* __restrict__ h, int off)
{
    constexpr int FO = P * 32;
    int gid  = blockIdx.x * blockDim.x + threadIdx.x;
    int row  = gid >> 5;
    int lane = gid & 31;
    const float cs = sqrtf(CC);

    float lam = g_lam[row];
    float w[P];
    float s = 0.f;
#pragma unroll
    for (int p = 0; p < P; p++) {
        int k = lane + 32 * p;
        float mm = m[(long long)row * FO + k];
        float zn = g_zn[off + k];
        float u  = cs * lam * mm / zn * g_chv[off + k] - (lam - 1.f) * g_shv[off + k];
        // cs*d = 2*zn*asinh(u); w = sinh(cs*d)/cs
        float ww = sinhf(2.f * zn * asinhf(u)) * (1.f / cs);
        w[p] = ww;
        s = fmaf(ww, ww, s);
    }
#pragma unroll
    for (int o = 16; o; o >>= 1) s += __shfl_xor_sync(0xffffffffu, s, o);

    float inv = 1.f / (1.f + sqrtf(1.f + CC * s));   // hlinear ball map: y = w * inv

    // hrelu: logmap0 -> relu -> expmap0 (fused, second warp reduction over positive part)
    float sp = 0.f;
#pragma unroll
    for (int p = 0; p < P; p++) {
        float y = w[p] * inv;
        w[p] = y;
        float yp = fmaxf(y, 0.f);
        sp = fmaf(yp, yp, sp);
    }
#pragma unroll
    for (int o = 16; o; o >>= 1) sp += __shfl_xor_sync(0xffffffffu, sp, o);

    float n  = fmaxf(sqrtf(s) * inv, 1e-15f);                 // ||y||
    float a  = atanhf(fminf(cs * n, 1.f - 1e-7f)) / (cs * n); // tangent scale
    float vn = fmaxf(a * sqrtf(sp), 1e-15f);                  // ||relu(v)||
    float fac = tanhf(cs * vn) / (cs * vn) * a;

#pragma unroll
    for (int p = 0; p < P; p++) {
        int k = lane + 32 * p;
        h[(long long)row * FO + k] = fac * fmaxf(w[p], 0.f);
    }
    if (lane == 0) {
        // ||h||^2 = tanh^2(cs*vn)/c  =>  lam_next = 2*cosh^2(cs*vn)
        float chv = coshf(cs * vn);
        g_lam[row] = 2.f * chv * chv;
    }
}

// ---------------- final layer fo=1: dot(h,z4) + hlinear epilogue ----------------
__global__ void final_kernel(const float* __restrict__ hin, const float* __restrict__ z4,
                             float* __restrict__ out)
{
    int gid  = blockIdx.x * blockDim.x + threadIdx.x;
    int row  = gid >> 5;
    int lane = gid & 31;
    float4 hv = ((const float4*)(hin + (long long)row * 128))[lane];
    float4 zv = ((const float4*)z4)[lane];
    float s = hv.x * zv.x + hv.y * zv.y + hv.z * zv.z + hv.w * zv.w;
#pragma unroll
    for (int o = 16; o; o >>= 1) s += __shfl_xor_sync(0xffffffffu, s, o);
    if (lane == 0) {
        const float cs = sqrtf(CC);
        float lam = g_lam[row];
        float zn  = g_zn[896];
        float u   = cs * lam * s / zn * g_chv[896] - (lam - 1.f) * g_shv[896];
        float w   = sinhf(2.f * zn * asinhf(u)) * (1.f / cs);
        out[row]  = w / (1.f + sqrtf(1.f + CC * w * w));
    }
}

// ---------------- launch ----------------
extern "C" void kernel_launch(void* const* d_in, const int* in_sizes, int n_in,
                              void* d_out, int out_size)
{
    const float* x  = (const float*)d_in[0];
    const float* z1 = (const float*)d_in[1];
    const float* b1 = (const float*)d_in[2];
    const float* z2 = (const float*)d_in[3];
    const float* b2 = (const float*)d_in[4];
    const float* z3 = (const float*)d_in[5];
    const float* b3 = (const float*)d_in[6];
    const float* z4 = (const float*)d_in[7];
    const float* b4 = (const float*)d_in[8];
    float* out = (float*)d_out;

    float *pm, *pA, *pB;
    cudaGetSymbolAddress((void**)&pm, g_m);
    cudaGetSymbolAddress((void**)&pA, g_hA);
    cudaGetSymbolAddress((void**)&pB, g_hB);

    const int warpBlocks = BATCH * 32 / 256;  // 8192: one warp per row

    lam0_kernel<<<warpBlocks, 256>>>(x);
    prep_kernel<<<2, 256>>>(z1, b1, 768, 512, 0);
    prep_kernel<<<1, 256>>>(z2, b2, 512, 256, 512);
    prep_kernel<<<1, 256>>>(z3, b3, 256, 128, 768);
    prep_kernel<<<1, 256>>>(z4, b4, 128, 1, 896);

    // layer 1: (B,768) @ (768,512)
    sgemm_kernel<<<dim3(512 / 64, BATCH / 128), 256>>>(x, z1, pm, BATCH, 512, 768);
    epi_kernel<16><<<warpBlocks, 256>>>(pm, pA, 0);

    // layer 2: (B,512) @ (512,256)
    sgemm_kernel<<<dim3(256 / 64, BATCH / 128), 256>>>(pA, z2, pm, BATCH, 256, 512);
    epi_kernel<8><<<warpBlocks, 256>>>(pm, pB, 512);

    // layer 3: (B,256) @ (256,128)
    sgemm_kernel<<<dim3(128 / 64, BATCH / 128), 256>>>(pB, z3, pm, BATCH, 128, 256);
    epi_kernel<4><<<warpBlocks, 256>>>(pm, pA, 768);

    // layer 4: (B,128) @ (128,1) + final ball map
    final_kernel<<<warpBlocks, 256>>>(pA, z4, out);
}

// round 2
// speedup vs baseline: 1.0015x; 1.0015x over previous
#include <cuda_runtime.h>
#include <math.h>

#define CC 2.3026f
#define BATCH 65536

// ---------------- static device scratch (allocation-free rule) ----------------
__device__ float g_m [(long long)BATCH * 512];  // gemm output buffer (reused)
__device__ float g_hA[(long long)BATCH * 512];  // hidden ping
__device__ float g_hB[(long long)BATCH * 256];  // hidden pong
__device__ float g_lam[BATCH];                  // conformal factor per row
// per-column precomputed tables: layer1 @0 (512), layer2 @512 (256), layer3 @768 (128), layer4 @896 (1)
__device__ float g_zn[897];
__device__ float g_chv[897];
__device__ float g_shv[897];

// ---------------- precompute zn = ||z_col||, cosh/sinh(2*cs*r) ----------------
__global__ void prep_kernel(const float* __restrict__ z, const float* __restrict__ r,
                            int fi, int fo, int off)
{
    int k = blockIdx.x * blockDim.x + threadIdx.x;
    if (k >= fo) return;
    float s = 0.f;
    for (int i = 0; i < fi; i++) {
        float v = z[(long long)i * fo + k];
        s = fmaf(v, v, s);
    }
    float zn = fmaxf(sqrtf(s), 1e-15f);
    const float cs = sqrtf(CC);
    float t = 2.f * cs * r[k];
    g_zn[off + k]  = zn;
    g_chv[off + k] = coshf(t);
    g_shv[off + k] = sinhf(t);
}

// ---------------- lam0 = 2 / (1 - c*||x||^2), warp per row (fi=768) ----------------
__global__ void lam0_kernel(const float* __restrict__ x)
{
    int gid  = blockIdx.x * blockDim.x + threadIdx.x;
    int row  = gid >> 5;
    int lane = gid & 31;
    const float4* xr = (const float4*)(x + (long long)row * 768);
    float s = 0.f;
#pragma unroll
    for (int p = 0; p < 6; p++) {
        float4 v = xr[lane + 32 * p];
        s += v.x * v.x + v.y * v.y + v.z * v.z + v.w * v.w;
    }
#pragma unroll
    for (int o = 16; o; o >>= 1) s += __shfl_xor_sync(0xffffffffu, s, o);
    if (lane == 0) g_lam[row] = 2.f / (1.f - CC * s);
}

// ---------------- SGEMM: C[M,N] = A[M,K] @ W[K,N], fp32 ----------------
// BM=128 BN=64 BK=16, 256 threads, thread tile 8x4
__global__ __launch_bounds__(256) void sgemm_kernel(
    const float* __restrict__ A, const float* __restrict__ W, float* __restrict__ Cm,
    int M, int N, int K)
{
    __shared__ float As[16][128];
    __shared__ float Ws[16][64];

    int tid = threadIdx.x;
    int bm = blockIdx.y * 128;
    int bn = blockIdx.x * 64;
    int tx = tid & 15;
    int ty = tid >> 4;

    float acc[8][4];
#pragma unroll
    for (int i = 0; i < 8; i++)
#pragma unroll
        for (int j = 0; j < 4; j++) acc[i][j] = 0.f;

    for (int k0 = 0; k0 < K; k0 += 16) {
        // load A tile: 128 rows x 16 cols = 512 float4, 2 per thread, transpose into As[k][m]
#pragma unroll
        for (int l = 0; l < 2; l++) {
            int idx = tid + 256 * l;
            int row = idx >> 2;
            int kq  = idx & 3;
            float4 a = *(const float4*)(A + (long long)(bm + row) * K + k0 + kq * 4);
            As[kq * 4 + 0][row] = a.x;
            As[kq * 4 + 1][row] = a.y;
            As[kq * 4 + 2][row] = a.z;
            As[kq * 4 + 3][row] = a.w;
        }
        // load W tile: 16 rows x 64 cols = 256 float4, 1 per thread
        {
            int row = tid >> 4;
            int cq  = tid & 15;
            float4 w = *(const float4*)(W + (long long)(k0 + row) * N + bn + cq * 4);
            *(float4*)&Ws[row][cq * 4] = w;
        }
        __syncthreads();

#pragma unroll
        for (int k = 0; k < 16; k++) {
            float a[8], b[4];
#pragma unroll
            for (int i = 0; i < 8; i++) a[i] = As[k][ty * 8 + i];
#pragma unroll
            for (int j = 0; j < 4; j++) b[j] = Ws[k][tx * 4 + j];
#pragma unroll
            for (int i = 0; i < 8; i++)
#pragma unroll
                for (int j = 0; j < 4; j++) acc[i][j] = fmaf(a[i], b[j], acc[i][j]);
        }
        __syncthreads();
    }

#pragma unroll
    for (int i = 0; i < 8; i++) {
        float4 v = make_float4(acc[i][0], acc[i][1], acc[i][2], acc[i][3]);
        *(float4*)(Cm + (long long)(bm + ty * 8 + i) * N + bn + tx * 4) = v;
    }
}

// ---------------- fused hlinear-epilogue + hrelu, warp per row ----------------
// P = fo/32 elements per lane. Also writes lam for the next layer.
template <int P>
__global__ void epi_kernel(const float* __restrict__ m, float* __restrict__ h, int off)
{
    constexpr int FO = P * 32;
    int gid  = blockIdx.x * blockDim.x + threadIdx.x;
    int row  = gid >> 5;
    int lane = gid & 31;
    const float cs = sqrtf(CC);

    float lam = g_lam[row];
    float w[P];
    float s = 0.f;
#pragma unroll
    for (int p = 0; p < P; p++) {
        int k = lane + 32 * p;
        float mm = m[(long long)row * FO + k];
        float zn = g_zn[off + k];
        float u  = cs * lam * mm / zn * g_chv[off + k] - (lam - 1.f) * g_shv[off + k];
        // cs*d = 2*zn*asinh(u); w = sinh(cs*d)/cs
        float ww = sinhf(2.f * zn * asinhf(u)) * (1.f / cs);
        w[p] = ww;
        s = fmaf(ww, ww, s);
    }
#pragma unroll
    for (int o = 16; o; o >>= 1) s += __shfl_xor_sync(0xffffffffu, s, o);

    float inv = 1.f / (1.f + sqrtf(1.f + CC * s));   // hlinear ball map: y = w * inv

    // hrelu: logmap0 -> relu -> expmap0 (fused, second warp reduction over positive part)
    float sp = 0.f;
#pragma unroll
    for (int p = 0; p < P; p++) {
        float y = w[p] * inv;
        w[p] = y;
        float yp = fmaxf(y, 0.f);
        sp = fmaf(yp, yp, sp);
    }
#pragma unroll
    for (int o = 16; o; o >>= 1) sp += __shfl_xor_sync(0xffffffffu, sp, o);

    float n  = fmaxf(sqrtf(s) * inv, 1e-15f);                 // ||y||
    float a  = atanhf(fminf(cs * n, 1.f - 1e-7f)) / (cs * n); // tangent scale
    float vn = fmaxf(a * sqrtf(sp), 1e-15f);                  // ||relu(v)||
    float fac = tanhf(cs * vn) / (cs * vn) * a;

#pragma unroll
    for (int p = 0; p < P; p++) {
        int k = lane + 32 * p;
        h[(long long)row * FO + k] = fac * fmaxf(w[p], 0.f);
    }
    if (lane == 0) {
        // ||h||^2 = tanh^2(cs*vn)/c  =>  lam_next = 2*cosh^2(cs*vn)
        float chv = coshf(cs * vn);
        g_lam[row] = 2.f * chv * chv;
    }
}

// ---------------- final layer fo=1: dot(h,z4) + hlinear epilogue ----------------
__global__ void final_kernel(const float* __restrict__ hin, const float* __restrict__ z4,
                             float* __restrict__ out)
{
    int gid  = blockIdx.x * blockDim.x + threadIdx.x;
    int row  = gid >> 5;
    int lane = gid & 31;
    float4 hv = ((const float4*)(hin + (long long)row * 128))[lane];
    float4 zv = ((const float4*)z4)[lane];
    float s = hv.x * zv.x + hv.y * zv.y + hv.z * zv.z + hv.w * zv.w;
#pragma unroll
    for (int o = 16; o; o >>= 1) s += __shfl_xor_sync(0xffffffffu, s, o);
    if (lane == 0) {
        const float cs = sqrtf(CC);
        float lam = g_lam[row];
        float zn  = g_zn[896];
        float u   = cs * lam * s / zn * g_chv[896] - (lam - 1.f) * g_shv[896];
        float w   = sinhf(2.f * zn * asinhf(u)) * (1.f / cs);
        out[row]  = w / (1.f + sqrtf(1.f + CC * w * w));
    }
}

// ---------------- launch ----------------
extern "C" void kernel_launch(void* const* d_in, const int* in_sizes, int n_in,
                              void* d_out, int out_size)
{
    const float* x  = (const float*)d_in[0];
    const float* z1 = (const float*)d_in[1];
    const float* b1 = (const float*)d_in[2];
    const float* z2 = (const float*)d_in[3];
    const float* b2 = (const float*)d_in[4];
    const float* z3 = (const float*)d_in[5];
    const float* b3 = (const float*)d_in[6];
    const float* z4 = (const float*)d_in[7];
    const float* b4 = (const float*)d_in[8];
    float* out = (float*)d_out;

    float *pm, *pA, *pB;
    cudaGetSymbolAddress((void**)&pm, g_m);
    cudaGetSymbolAddress((void**)&pA, g_hA);
    cudaGetSymbolAddress((void**)&pB, g_hB);

    const int warpBlocks = BATCH * 32 / 256;  // 8192: one warp per row

    lam0_kernel<<<warpBlocks, 256>>>(x);
    prep_kernel<<<2, 256>>>(z1, b1, 768, 512, 0);
    prep_kernel<<<1, 256>>>(z2, b2, 512, 256, 512);
    prep_kernel<<<1, 256>>>(z3, b3, 256, 128, 768);
    prep_kernel<<<1, 256>>>(z4, b4, 128, 1, 896);

    // layer 1: (B,768) @ (768,512)
    sgemm_kernel<<<dim3(512 / 64, BATCH / 128), 256>>>(x, z1, pm, BATCH, 512, 768);
    epi_kernel<16><<<warpBlocks, 256>>>(pm, pA, 0);

    // layer 2: (B,512) @ (512,256)
    sgemm_kernel<<<dim3(256 / 64, BATCH / 128), 256>>>(pA, z2, pm, BATCH, 256, 512);
    epi_kernel<8><<<warpBlocks, 256>>>(pm, pB, 512);

    // layer 3: (B,256) @ (256,128)
    sgemm_kernel<<<dim3(128 / 64, BATCH / 128), 256>>>(pB, z3, pm, BATCH, 128, 256);
    epi_kernel<4><<<warpBlocks, 256>>>(pm, pA, 768);

    // layer 4: (B,128) @ (128,1) + final ball map
    final_kernel<<<warpBlocks, 256>>>(pA, z4, out);
}